// round 6
// baseline (speedup 1.0000x reference)
#include <cuda_runtime.h>
#include <cuda_bf16.h>
#include <cuda_fp8.h>
#include <math.h>
#include <stdint.h>

#define BATCH 8
#define SEQ   2048
#define DIM   512
#define SH    128
#define EXP   1024
#define PROJ  2176
#define NROWS (BATCH * SEQ)

#define BMT 128
#define STAGES 4

// scales (powers of 2)
#define S_X    8.f
#define S_W    64.f
#define S_QK   64.f
#define S_ATT  4096.f
#define S_V    16.f
#define S_O    1024.f

// -------------------- scratch --------------------
__device__ alignas(16) uint8_t        g_xnf[NROWS * DIM];
__device__ alignas(16) __nv_bfloat16  g_uvb[(size_t)NROWS * PROJ];
__device__ alignas(16) uint8_t        g_w1f[(size_t)PROJ * DIM];
__device__ alignas(16) uint8_t        g_w2f[(size_t)DIM * EXP];
__device__ alignas(16) uint8_t        g_qf [NROWS * SH];
__device__ alignas(16) uint8_t        g_kf [NROWS * SH];
__device__ alignas(16) uint8_t        g_attf[(size_t)BATCH * SEQ * SEQ];
__device__ alignas(16) uint8_t        g_vtf [(size_t)BATCH * EXP * SEQ];
__device__ alignas(16) uint8_t        g_of  [(size_t)NROWS * EXP];
__device__ float g_f[2 * SEQ - 1];

// -------------------- helpers --------------------
__device__ __forceinline__ uint32_t smem_u32(const void* p) {
    uint32_t a;
    asm("{ .reg .u64 t; cvta.to.shared.u64 t, %1; cvt.u32.u64 %0, t; }" : "=r"(a) : "l"(p));
    return a;
}
__device__ __forceinline__ void cp16s(uint32_t saddr, const void* g) {
    asm volatile("cp.async.cg.shared.global [%0], [%1], 16;\n" :: "r"(saddr), "l"(g));
}
#define CP_COMMIT() asm volatile("cp.async.commit_group;\n" ::: "memory")
#define SWZ(o) ((o) ^ (((o) >> 3) & 0x70))

__device__ __forceinline__ void qmma(float* c, const uint32_t* a, const uint32_t* b) {
    asm volatile(
        "mma.sync.aligned.m16n8k32.row.col.f32.e4m3.e4m3.f32 "
        "{%0,%1,%2,%3},{%4,%5,%6,%7},{%8,%9},{%0,%1,%2,%3};\n"
        : "+f"(c[0]), "+f"(c[1]), "+f"(c[2]), "+f"(c[3])
        : "r"(a[0]), "r"(a[1]), "r"(a[2]), "r"(a[3]), "r"(b[0]), "r"(b[1]));
}
__device__ __forceinline__ void ldsm4(uint32_t* r, uint32_t addr) {
    asm volatile("ldmatrix.sync.aligned.m8n8.x4.shared.b16 {%0,%1,%2,%3}, [%4];"
        : "=r"(r[0]), "=r"(r[1]), "=r"(r[2]), "=r"(r[3]) : "r"(addr));
}
// pack two floats to 2 e4m3 bytes; lo -> low byte of result
__device__ __forceinline__ uint16_t f2e4m3x2(float lo, float hi) {
    uint16_t r;
    asm("cvt.rn.satfinite.e4m3x2.f32 %0, %1, %2;" : "=h"(r) : "f"(hi), "f"(lo));
    return r;
}
__device__ __forceinline__ uint8_t f2e4m3(float v) {
    return (uint8_t)__nv_cvt_float_to_fp8(v, __NV_SATFINITE, __NV_E4M3);
}

// -------------------- prep kernels --------------------
__global__ void rmsnorm_kernel(const float* __restrict__ x,
                               const float* __restrict__ ns_p) {
    int row = blockIdx.x;
    const float* xr = x + (size_t)row * DIM;
    uint8_t* outr = g_xnf + (size_t)row * DIM;
    float s = 0.f;
    for (int i = threadIdx.x; i < DIM; i += blockDim.x) { float v = xr[i]; s += v * v; }
    __shared__ float warp_s[4];
    #pragma unroll
    for (int off = 16; off > 0; off >>= 1) s += __shfl_down_sync(0xffffffffu, s, off);
    int lane = threadIdx.x & 31, wid = threadIdx.x >> 5;
    if (lane == 0) warp_s[wid] = s;
    __syncthreads();
    if (wid == 0) {
        float t = (lane < 4) ? warp_s[lane] : 0.f;
        #pragma unroll
        for (int off = 2; off > 0; off >>= 1) t += __shfl_down_sync(0xffffffffu, t, off);
        if (lane == 0) warp_s[0] = t;
    }
    __syncthreads();
    float scale = rsqrtf(warp_s[0] * (1.f / (float)DIM) + 1e-6f) * ns_p[0] * S_X;
    for (int i = threadIdx.x; i < DIM; i += blockDim.x)
        outr[i] = f2e4m3(xr[i] * scale);
}

__global__ void toeplitz_kernel(const float* __restrict__ a,
                                const float* __restrict__ b) {
    __shared__ float sp[SEQ / 2];
    __shared__ float sr[SEQ / 2];
    for (int i = threadIdx.x; i < SEQ / 2; i += blockDim.x) {
        float a1 = a[i], a2 = a[i + SEQ / 2];
        float b1v = b[i], b2v = b[i + SEQ / 2];
        sp[i] = a1 * b1v + a2 * b2v;
        sr[i] = a2 * b1v - a1 * b2v;
    }
    __syncthreads();
    int d = blockIdx.x * blockDim.x + threadIdx.x;
    if (d >= SEQ) return;
    float sumc = 0.f, sums = 0.f;
    const float log1e4 = 9.210340371976184f;
    for (int i = 0; i < SEQ / 2; i++) {
        float theta = expf(-((float)i * (1.f / (SEQ / 2))) * log1e4);
        float s, c;
        sincosf((float)d * theta, &s, &c);
        sumc += sp[i] * c;
        sums += sr[i] * s;
    }
    g_f[(SEQ - 1) + d] = sumc - sums;
    g_f[(SEQ - 1) - d] = sumc + sums;
}

// transpose fp32 -> fp8 with scale; out[c][r] = in[r][c]*scale
__global__ void wtrans_kernel(const float* __restrict__ in, uint8_t* __restrict__ out,
                              int rows, int cols, float scale) {
    __shared__ float t[32][33];
    int r0 = blockIdx.y * 32, c0 = blockIdx.x * 32;
    int tx = threadIdx.x & 31, ty = threadIdx.x >> 5;
    #pragma unroll
    for (int i = ty; i < 32; i += 8)
        t[i][tx] = in[(size_t)(r0 + i) * cols + c0 + tx];
    __syncthreads();
    #pragma unroll
    for (int i = ty; i < 32; i += 8)
        out[(size_t)(c0 + i) * rows + r0 + tx] = f2e4m3(t[tx][i] * scale);
}

__global__ void vtrans_kernel() {
    __shared__ float t[32][33];
    int z = blockIdx.z;
    int s0 = blockIdx.x * 32, e0 = blockIdx.y * 32;
    int tx = threadIdx.x & 31, ty = threadIdx.x >> 5;
    #pragma unroll
    for (int i = ty; i < 32; i += 8)
        t[i][tx] = __bfloat162float(g_uvb[(size_t)(z * SEQ + s0 + i) * PROJ + EXP + e0 + tx]);
    __syncthreads();
    #pragma unroll
    for (int i = ty; i < 32; i += 8)
        g_vtf[((size_t)z * EXP + e0 + i) * SEQ + s0 + tx] = f2e4m3(t[tx][i] * S_V);
}

__global__ void qkgen_kernel(const float* __restrict__ gamma,
                             const float* __restrict__ beta) {
    int idx = blockIdx.x * blockDim.x + threadIdx.x;
    int j = idx & (SH - 1);
    int row = idx >> 7;
    float base = __bfloat162float(g_uvb[(size_t)row * PROJ + 2 * EXP + j]);
    g_qf[idx] = f2e4m3((base * gamma[j] + beta[j]) * S_QK);
    g_kf[idx] = f2e4m3((base * gamma[SH + j] + beta[SH + j]) * S_QK);
}

// -------------------- FP8 QMMA NT GEMM, ldmatrix + 4-stage pipeline ------
// C[m][n] = sum_k A[m][k]*B[n][k]; byte strides; K-tile = 128 bytes (128 fp8)
enum { EPI_G1 = 0, EPI_ATT = 1, EPI_O = 2, EPI_OUT = 3 };

template <int BN, int EPI>
__global__ void __launch_bounds__(256, 1) q_gemm(
    const uint8_t* __restrict__ A, int lda, long long strideA,
    const uint8_t* __restrict__ Bm, int ldb, long long strideB,
    void* __restrict__ Cout, int ldc, long long strideC,
    int KT,
    const float* __restrict__ bias,
    const float* __restrict__ resid) {
    constexpr int NW_N = BN / 64;
    constexpr int NW_M = 8 / NW_N;
    constexpr int MT = BMT / (NW_M * 16);
    constexpr int A_BYTES = BMT * 128;
    constexpr int B_BYTES = BN * 128;
    constexpr int STAGE_BYTES = A_BYTES + B_BYTES;

    extern __shared__ char smem[];
    uint32_t sb = (smem_u32(smem) + 1023) & ~1023u;
    int t = threadIdx.x;
    int warp = t >> 5, lane = t & 31;
    int wn = warp % NW_N, wm = warp / NW_N;
    int z = blockIdx.z;

    const uint8_t* Ag = A + (long long)z * strideA + (long long)(blockIdx.y * BMT) * lda;
    const uint8_t* Bg = Bm + (long long)z * strideB + (long long)(blockIdx.x * BN) * ldb;

    uint32_t a_off = (uint32_t)((wm * MT * 16 + (lane & 15)) * 128 + (lane & 16));
    uint32_t b_off = (uint32_t)((wn * 64 + (lane & 7) + ((lane >> 1) & 8)) * 128 + (lane & 8) * 2);

    auto load_tile = [&](int j) {
        int s = j % STAGES;
        uint32_t sA = sb + s * STAGE_BYTES;
        uint32_t sB = sA + A_BYTES;
        const uint8_t* Asrc = Ag + j * 128;
        const uint8_t* Bsrc = Bg + j * 128;
        #pragma unroll
        for (int i = 0; i < (BMT * 8) / 256; i++) {
            int c = t + i * 256;
            int row = c >> 3, kc = c & 7;
            cp16s(sA + SWZ(row * 128 + kc * 16), Asrc + (long long)row * lda + kc * 16);
        }
        #pragma unroll
        for (int i = 0; i < (BN * 8) / 256; i++) {
            int c = t + i * 256;
            int row = c >> 3, kc = c & 7;
            cp16s(sB + SWZ(row * 128 + kc * 16), Bsrc + (long long)row * ldb + kc * 16);
        }
        CP_COMMIT();
    };

    float acc[MT][8][4];
    #pragma unroll
    for (int i = 0; i < MT; i++)
        #pragma unroll
        for (int j = 0; j < 8; j++)
            #pragma unroll
            for (int l = 0; l < 4; l++) acc[i][j][l] = 0.f;

    #pragma unroll
    for (int j = 0; j < STAGES - 1; j++)
        if (j < KT) load_tile(j);

    for (int kt = 0; kt < KT; kt++) {
        int committed = (kt + STAGES - 1 < KT) ? (kt + STAGES - 1) : KT;
        int pend = committed - kt - 1;
        if (pend >= 2)      asm volatile("cp.async.wait_group 2;\n" ::: "memory");
        else if (pend == 1) asm volatile("cp.async.wait_group 1;\n" ::: "memory");
        else                asm volatile("cp.async.wait_group 0;\n" ::: "memory");
        __syncthreads();

        int j = kt + STAGES - 1;
        if (j < KT) load_tile(j);

        int s = kt % STAGES;
        uint32_t sA = sb + s * STAGE_BYTES;
        uint32_t sB = sA + A_BYTES;
        #pragma unroll
        for (int ks = 0; ks < 4; ks++) {      // 4 x k32 fp8 = 128 bytes
            uint32_t a[MT][4], b[8][2];
            #pragma unroll
            for (int mt = 0; mt < MT; mt++)
                ldsm4(a[mt], sA + SWZ(a_off + mt * 2048 + ks * 32));
            #pragma unroll
            for (int i = 0; i < 4; i++) {
                uint32_t r[4];
                ldsm4(r, sB + SWZ(b_off + i * 2048 + ks * 32));
                b[2 * i][0] = r[0]; b[2 * i][1] = r[1];
                b[2 * i + 1][0] = r[2]; b[2 * i + 1][1] = r[3];
            }
            #pragma unroll
            for (int mt = 0; mt < MT; mt++)
                #pragma unroll
                for (int nt = 0; nt < 8; nt++) qmma(acc[mt][nt], a[mt], b[nt]);
        }
    }

    // -------- epilogue --------
    int fr = lane >> 2, fc = (lane & 3) * 2;
    int bm0 = blockIdx.y * BMT + wm * MT * 16;
    int bn0 = blockIdx.x * BN + wn * 64;
    #pragma unroll
    for (int mt = 0; mt < MT; mt++) {
        #pragma unroll
        for (int nt = 0; nt < 8; nt++) {
            #pragma unroll
            for (int half = 0; half < 2; half++) {
                int gm = bm0 + mt * 16 + fr + half * 8;
                int gn = bn0 + nt * 8 + fc;
                float v0 = acc[mt][nt][half * 2 + 0];
                float v1 = acc[mt][nt][half * 2 + 1];
                if (EPI == EPI_G1) {
                    // acc = (x*8)@(W1*64) -> /512 ; + b1 ; swish -> bf16
                    float c0 = v0 * (1.f / 512.f) + bias[gn];
                    float c1 = v1 * (1.f / 512.f) + bias[gn + 1];
                    c0 = c0 / (1.f + expf(-c0));
                    c1 = c1 / (1.f + expf(-c1));
                    __nv_bfloat162 h2;
                    h2.x = __float2bfloat16(c0);
                    h2.y = __float2bfloat16(c1);
                    *(__nv_bfloat162*)((__nv_bfloat16*)Cout + (size_t)gm * ldc + gn) = h2;
                } else if (EPI == EPI_ATT) {
                    // rs = 64*(acc/4096/2048 + f) ; att_fp8 = rs^2 = att*4096
                    float r0 = v0 * (1.f / 131072.f) + S_QK * g_f[gm - gn + (SEQ - 1)];
                    float r1 = v1 * (1.f / 131072.f) + S_QK * g_f[gm - gn - 1 + (SEQ - 1)];
                    r0 = fmaxf(r0, 0.f);
                    r1 = fmaxf(r1, 0.f);
                    uint8_t* cp = (uint8_t*)Cout + (long long)z * strideC;
                    *(uint16_t*)(cp + (size_t)gm * ldc + gn) = f2e4m3x2(r0 * r0, r1 * r1);
                } else if (EPI == EPI_O) {
                    // acc = (att*4096)@(v*16) ; o_fp8 = acc/65536*u*1024 = acc/64*u
                    float u0 = __bfloat162float(g_uvb[(size_t)(z * SEQ + gm) * PROJ + gn]);
                    float u1 = __bfloat162float(g_uvb[(size_t)(z * SEQ + gm) * PROJ + gn + 1]);
                    uint8_t* cp = (uint8_t*)Cout + (long long)z * strideC;
                    *(uint16_t*)(cp + (size_t)gm * ldc + gn) =
                        f2e4m3x2(v0 * (1.f / 64.f) * u0, v1 * (1.f / 64.f) * u1);
                } else {
                    // acc = (o*1024)@(W2*64) -> /65536 ; + b2 + x
                    float c0 = v0 * (1.f / 65536.f) + bias[gn] + resid[(size_t)gm * DIM + gn];
                    float c1 = v1 * (1.f / 65536.f) + bias[gn + 1] + resid[(size_t)gm * DIM + gn + 1];
                    *(float2*)((float*)Cout + (size_t)gm * ldc + gn) = make_float2(c0, c1);
                }
            }
        }
    }
}

// -------------------- launch --------------------
extern "C" void kernel_launch(void* const* d_in, const int* in_sizes, int n_in,
                              void* d_out, int out_size) {
    const float* x          = (const float*)d_in[0];
    const float* W1         = (const float*)d_in[1];
    const float* b1         = (const float*)d_in[2];
    const float* W2         = (const float*)d_in[3];
    const float* b2         = (const float*)d_in[4];
    const float* rope_a     = (const float*)d_in[5];
    const float* rope_b     = (const float*)d_in[6];
    const float* gamma      = (const float*)d_in[7];
    const float* beta       = (const float*)d_in[8];
    const float* norm_scale = (const float*)d_in[9];
    float* out = (float*)d_out;

    void *p_xnf, *p_uvb, *p_w1f, *p_w2f, *p_qf, *p_kf, *p_attf, *p_vtf, *p_of;
    cudaGetSymbolAddress(&p_xnf, g_xnf);
    cudaGetSymbolAddress(&p_uvb, g_uvb);
    cudaGetSymbolAddress(&p_w1f, g_w1f);
    cudaGetSymbolAddress(&p_w2f, g_w2f);
    cudaGetSymbolAddress(&p_qf, g_qf);
    cudaGetSymbolAddress(&p_kf, g_kf);
    cudaGetSymbolAddress(&p_attf, g_attf);
    cudaGetSymbolAddress(&p_vtf, g_vtf);
    cudaGetSymbolAddress(&p_of, g_of);

    constexpr int SM128 = 1024 + STAGES * (BMT * 128 + 128 * 128);   // ~129KB
    constexpr int SM256 = 1024 + STAGES * (BMT * 128 + 256 * 128);   // ~193KB
    cudaFuncSetAttribute(q_gemm<128, EPI_G1>,  cudaFuncAttributeMaxDynamicSharedMemorySize, SM128);
    cudaFuncSetAttribute(q_gemm<256, EPI_ATT>, cudaFuncAttributeMaxDynamicSharedMemorySize, SM256);
    cudaFuncSetAttribute(q_gemm<256, EPI_O>,   cudaFuncAttributeMaxDynamicSharedMemorySize, SM256);
    cudaFuncSetAttribute(q_gemm<256, EPI_OUT>, cudaFuncAttributeMaxDynamicSharedMemorySize, SM256);

    rmsnorm_kernel <<<NROWS, 128>>>(x, norm_scale);
    toeplitz_kernel<<<SEQ / 256, 256>>>(rope_a, rope_b);
    wtrans_kernel  <<<dim3(PROJ / 32, DIM / 32), 256>>>(W1, (uint8_t*)p_w1f, DIM, PROJ, S_W);
    wtrans_kernel  <<<dim3(DIM / 32, EXP / 32), 256>>>(W2, (uint8_t*)p_w2f, EXP, DIM, S_W);

    // uv = swish(xn @ W1 + b1)     M=16384 N=2176 K=512 (KT=4)
    q_gemm<128, EPI_G1><<<dim3(PROJ / 128, NROWS / BMT, 1), 256, SM128>>>(
        (const uint8_t*)p_xnf, DIM, 0,
        (const uint8_t*)p_w1f, DIM, 0,
        p_uvb, PROJ, 0, DIM / 128, b1, nullptr);

    qkgen_kernel <<<NROWS * SH / 256, 256>>>(gamma, beta);
    vtrans_kernel<<<dim3(SEQ / 32, EXP / 32, BATCH), 256>>>();

    // att = relu(q@k^T/SEQ + f)^2  per batch M=N=2048 K=128 (KT=1)
    q_gemm<256, EPI_ATT><<<dim3(SEQ / 256, SEQ / BMT, BATCH), 256, SM256>>>(
        (const uint8_t*)p_qf, SH, (long long)SEQ * SH,
        (const uint8_t*)p_kf, SH, (long long)SEQ * SH,
        p_attf, SEQ, (long long)SEQ * SEQ, SH / 128, nullptr, nullptr);

    // o = u * (att @ v)            per batch M=2048 N=1024 K=2048 (KT=16)
    q_gemm<256, EPI_O><<<dim3(EXP / 256, SEQ / BMT, BATCH), 256, SM256>>>(
        (const uint8_t*)p_attf, SEQ, (long long)SEQ * SEQ,
        (const uint8_t*)p_vtf, SEQ, (long long)EXP * SEQ,
        p_of, EXP, (long long)SEQ * EXP, SEQ / 128, nullptr, nullptr);

    // out = o @ W2 + b2 + x        M=16384 N=512 K=1024 (KT=8)
    q_gemm<256, EPI_OUT><<<dim3(DIM / 256, NROWS / BMT, 1), 256, SM256>>>(
        (const uint8_t*)p_of, EXP, 0,
        (const uint8_t*)p_w2f, EXP, 0,
        out, DIM, 0, EXP / 128, b2, x);
}

// round 7
// speedup vs baseline: 1.3307x; 1.3307x over previous
#include <cuda_runtime.h>
#include <cuda_bf16.h>
#include <math.h>
#include <stdint.h>

#define BATCH 8
#define SEQ   2048
#define DIM   512
#define SH    128
#define EXP   1024
#define PROJ  2176
#define NROWS (BATCH * SEQ)

#define BMT 128
#define BKT 64
#define STAGES 3

// -------------------- scratch --------------------
__device__ alignas(16) __nv_bfloat16 g_xnb[NROWS * DIM];
__device__ alignas(16) __nv_bfloat16 g_uvb[(size_t)NROWS * PROJ];
__device__ alignas(16) __nv_bfloat16 g_w1t[(size_t)PROJ * DIM];
__device__ alignas(16) __nv_bfloat16 g_w2t[(size_t)DIM * EXP];
__device__ alignas(16) __nv_bfloat16 g_qb [NROWS * SH];
__device__ alignas(16) __nv_bfloat16 g_kb [NROWS * SH];
__device__ alignas(16) __nv_bfloat16 g_attb[(size_t)BATCH * SEQ * SEQ];
__device__ alignas(16) __nv_bfloat16 g_vtb [(size_t)BATCH * EXP * SEQ];
__device__ alignas(16) __nv_bfloat16 g_ob  [(size_t)NROWS * EXP];
__device__ float g_f[2 * SEQ - 1];

// -------------------- helpers --------------------
__device__ __forceinline__ uint32_t smem_u32(const void* p) {
    uint32_t a;
    asm("{ .reg .u64 t; cvta.to.shared.u64 t, %1; cvt.u32.u64 %0, t; }" : "=r"(a) : "l"(p));
    return a;
}
__device__ __forceinline__ void cp16s(uint32_t saddr, const void* g) {
    asm volatile("cp.async.cg.shared.global [%0], [%1], 16;\n" :: "r"(saddr), "l"(g));
}
#define CP_COMMIT() asm volatile("cp.async.commit_group;\n" ::: "memory")
#define SWZ(o) ((o) ^ (((o) >> 3) & 0x70))

__device__ __forceinline__ void mma16816(float* c, const uint32_t* a, const uint32_t* b) {
    asm volatile(
        "mma.sync.aligned.m16n8k16.row.col.f32.bf16.bf16.f32 "
        "{%0,%1,%2,%3},{%4,%5,%6,%7},{%8,%9},{%0,%1,%2,%3};\n"
        : "+f"(c[0]), "+f"(c[1]), "+f"(c[2]), "+f"(c[3])
        : "r"(a[0]), "r"(a[1]), "r"(a[2]), "r"(a[3]), "r"(b[0]), "r"(b[1]));
}
__device__ __forceinline__ void ldsm4(uint32_t* r, uint32_t addr) {
    asm volatile("ldmatrix.sync.aligned.m8n8.x4.shared.b16 {%0,%1,%2,%3}, [%4];"
        : "=r"(r[0]), "=r"(r[1]), "=r"(r[2]), "=r"(r[3]) : "r"(addr));
}

// -------------------- kernel 0: rmsnorm -> bf16 --------------------
__global__ void rmsnorm_kernel(const float* __restrict__ x,
                               const float* __restrict__ ns_p) {
    int row = blockIdx.x;
    const float* xr = x + (size_t)row * DIM;
    __nv_bfloat16* outr = g_xnb + (size_t)row * DIM;
    float s = 0.f;
    for (int i = threadIdx.x; i < DIM; i += blockDim.x) { float v = xr[i]; s += v * v; }
    __shared__ float warp_s[4];
    #pragma unroll
    for (int off = 16; off > 0; off >>= 1) s += __shfl_down_sync(0xffffffffu, s, off);
    int lane = threadIdx.x & 31, wid = threadIdx.x >> 5;
    if (lane == 0) warp_s[wid] = s;
    __syncthreads();
    if (wid == 0) {
        float t = (lane < 4) ? warp_s[lane] : 0.f;
        #pragma unroll
        for (int off = 2; off > 0; off >>= 1) t += __shfl_down_sync(0xffffffffu, t, off);
        if (lane == 0) warp_s[0] = t;
    }
    __syncthreads();
    float scale = rsqrtf(warp_s[0] * (1.f / (float)DIM) + 1e-6f) * ns_p[0];
    for (int i = threadIdx.x; i < DIM; i += blockDim.x)
        outr[i] = __float2bfloat16(xr[i] * scale);
}

// -------------------- kernel 1: toeplitz + W1^T + W2^T (fused) ------------
__global__ void prep2_kernel(const float* __restrict__ W1, const float* __restrict__ W2,
                             const float* __restrict__ ra, const float* __restrict__ rb) {
    __shared__ float sp[SEQ / 2];
    __shared__ float sr[SEQ / 2];
    __shared__ float tt[32][33];
    int bx = blockIdx.x;
    if (bx < 8) {
        // toeplitz
        for (int i = threadIdx.x; i < SEQ / 2; i += blockDim.x) {
            float a1 = ra[i], a2 = ra[i + SEQ / 2];
            float b1v = rb[i], b2v = rb[i + SEQ / 2];
            sp[i] = a1 * b1v + a2 * b2v;
            sr[i] = a2 * b1v - a1 * b2v;
        }
        __syncthreads();
        int d = bx * 256 + threadIdx.x;
        float sumc = 0.f, sums = 0.f;
        const float log1e4 = 9.210340371976184f;
        for (int i = 0; i < SEQ / 2; i++) {
            float theta = expf(-((float)i * (1.f / (SEQ / 2))) * log1e4);
            float s, c;
            sincosf((float)d * theta, &s, &c);
            sumc += sp[i] * c;
            sums += sr[i] * s;
        }
        g_f[(SEQ - 1) + d] = sumc - sums;
        g_f[(SEQ - 1) - d] = sumc + sums;
        return;
    }
    const float* in;
    __nv_bfloat16* out;
    int rows, cols, bxx, byy;
    if (bx < 8 + (PROJ / 32) * (DIM / 32)) {
        int b = bx - 8;
        in = W1; out = g_w1t; rows = DIM; cols = PROJ;
        bxx = b % (PROJ / 32); byy = b / (PROJ / 32);
    } else {
        int b = bx - 8 - (PROJ / 32) * (DIM / 32);
        in = W2; out = g_w2t; rows = EXP; cols = DIM;
        bxx = b % (DIM / 32); byy = b / (DIM / 32);
    }
    int r0 = byy * 32, c0 = bxx * 32;
    int tx = threadIdx.x & 31, ty = threadIdx.x >> 5;
    #pragma unroll
    for (int i = ty; i < 32; i += 8)
        tt[i][tx] = in[(size_t)(r0 + i) * cols + c0 + tx];
    __syncthreads();
    #pragma unroll
    for (int i = ty; i < 32; i += 8)
        out[(size_t)(c0 + i) * rows + r0 + tx] = __float2bfloat16(tt[tx][i]);
}

// -------------------- kernel 3: qkgen + vtrans (fused) --------------------
__global__ void qkv_kernel(const float* __restrict__ gamma,
                           const float* __restrict__ beta) {
    __shared__ __nv_bfloat16 t[32][33];
    int bx = blockIdx.x;
    if (bx < (NROWS * SH) / 256) {
        int idx = bx * 256 + threadIdx.x;
        int j = idx & (SH - 1);
        int row = idx >> 7;
        float base = __bfloat162float(g_uvb[(size_t)row * PROJ + 2 * EXP + j]);
        g_qb[idx] = __float2bfloat16(base * gamma[j] + beta[j]);
        g_kb[idx] = __float2bfloat16(base * gamma[SH + j] + beta[SH + j]);
        return;
    }
    int b = bx - (NROWS * SH) / 256;
    int s0 = (b % (SEQ / 32)) * 32;
    int e0 = ((b / (SEQ / 32)) % (EXP / 32)) * 32;
    int z = b / ((SEQ / 32) * (EXP / 32));
    int tx = threadIdx.x & 31, ty = threadIdx.x >> 5;
    #pragma unroll
    for (int i = ty; i < 32; i += 8)
        t[i][tx] = g_uvb[(size_t)(z * SEQ + s0 + i) * PROJ + EXP + e0 + tx];
    __syncthreads();
    #pragma unroll
    for (int i = ty; i < 32; i += 8)
        g_vtb[((size_t)z * EXP + e0 + i) * SEQ + s0 + tx] = t[tx][i];
}

// -------------------- HMMA NT GEMM, BN=128, 3 stages, 2 CTA/SM ------------
enum { EPI_G1 = 0, EPI_ATT = 1, EPI_O = 2, EPI_OUT = 3 };

template <int EPI>
__global__ void __launch_bounds__(256, 2) tc_gemm(
    const __nv_bfloat16* __restrict__ A, int lda, long long strideA,
    const __nv_bfloat16* __restrict__ Bm, int ldb, long long strideB,
    void* __restrict__ Cout, int ldc, long long strideC,
    int KT,
    const float* __restrict__ bias,
    const float* __restrict__ resid) {
    constexpr int BN = 128;
    constexpr int NW_N = 2;                  // warps along N (64 cols each)
    constexpr int NW_M = 4;                  // warps along M (32 rows each)
    constexpr int MT = 2;                    // 16-row m-tiles per warp
    constexpr int A_BYTES = BMT * 128;       // 16KB
    constexpr int B_BYTES = BN * 128;        // 16KB
    constexpr int STAGE_BYTES = A_BYTES + B_BYTES;

    extern __shared__ char smem[];
    uint32_t sb = (smem_u32(smem) + 1023) & ~1023u;
    int t = threadIdx.x;
    int warp = t >> 5, lane = t & 31;
    int wn = warp & 1, wm = warp >> 1;
    int z = blockIdx.z;

    const __nv_bfloat16* Ag = A + (long long)z * strideA + (long long)(blockIdx.y * BMT) * lda;
    const __nv_bfloat16* Bg = Bm + (long long)z * strideB + (long long)(blockIdx.x * BN) * ldb;

    uint32_t a_off = (uint32_t)((wm * MT * 16 + (lane & 15)) * 128 + (lane & 16));
    uint32_t b_off = (uint32_t)((wn * 64 + (lane & 7) + ((lane >> 1) & 8)) * 128 + (lane & 8) * 2);

    auto load_tile = [&](int j) {
        int s = j % STAGES;
        uint32_t sA = sb + s * STAGE_BYTES;
        uint32_t sB = sA + A_BYTES;
        const __nv_bfloat16* Asrc = Ag + j * BKT;
        const __nv_bfloat16* Bsrc = Bg + j * BKT;
        #pragma unroll
        for (int i = 0; i < 4; i++) {
            int c = t + i * 256;
            int row = c >> 3, kc = c & 7;
            cp16s(sA + SWZ(row * 128 + kc * 16), Asrc + (long long)row * lda + kc * 8);
        }
        #pragma unroll
        for (int i = 0; i < 4; i++) {
            int c = t + i * 256;
            int row = c >> 3, kc = c & 7;
            cp16s(sB + SWZ(row * 128 + kc * 16), Bsrc + (long long)row * ldb + kc * 8);
        }
        CP_COMMIT();
    };

    float acc[MT][8][4];
    #pragma unroll
    for (int i = 0; i < MT; i++)
        #pragma unroll
        for (int j = 0; j < 8; j++)
            #pragma unroll
            for (int l = 0; l < 4; l++) acc[i][j][l] = 0.f;

    load_tile(0);
    if (KT > 1) load_tile(1);

    for (int kt = 0; kt < KT; kt++) {
        if (kt + 1 < KT) asm volatile("cp.async.wait_group 1;\n" ::: "memory");
        else             asm volatile("cp.async.wait_group 0;\n" ::: "memory");
        __syncthreads();

        if (kt + 2 < KT) load_tile(kt + 2);

        int s = kt % STAGES;
        uint32_t sA = sb + s * STAGE_BYTES;
        uint32_t sB = sA + A_BYTES;
        #pragma unroll
        for (int ks = 0; ks < 4; ks++) {
            uint32_t a[MT][4], b[8][2];
            #pragma unroll
            for (int mt = 0; mt < MT; mt++)
                ldsm4(a[mt], sA + SWZ(a_off + mt * 2048 + ks * 32));
            #pragma unroll
            for (int i = 0; i < 4; i++) {
                uint32_t r[4];
                ldsm4(r, sB + SWZ(b_off + i * 2048 + ks * 32));
                b[2 * i][0] = r[0]; b[2 * i][1] = r[1];
                b[2 * i + 1][0] = r[2]; b[2 * i + 1][1] = r[3];
            }
            #pragma unroll
            for (int mt = 0; mt < MT; mt++)
                #pragma unroll
                for (int nt = 0; nt < 8; nt++) mma16816(acc[mt][nt], a[mt], b[nt]);
        }
    }

    // -------- epilogue --------
    int fr = lane >> 2, fc = (lane & 3) * 2;
    int bm0 = blockIdx.y * BMT + wm * MT * 16;
    int bn0 = blockIdx.x * BN + wn * 64;
    #pragma unroll
    for (int mt = 0; mt < MT; mt++) {
        #pragma unroll
        for (int nt = 0; nt < 8; nt++) {
            #pragma unroll
            for (int half = 0; half < 2; half++) {
                int gm = bm0 + mt * 16 + fr + half * 8;
                int gn = bn0 + nt * 8 + fc;
                float v0 = acc[mt][nt][half * 2 + 0];
                float v1 = acc[mt][nt][half * 2 + 1];
                if (EPI == EPI_G1) {
                    float c0 = v0 + bias[gn], c1 = v1 + bias[gn + 1];
                    c0 = c0 / (1.f + expf(-c0));
                    c1 = c1 / (1.f + expf(-c1));
                    __nv_bfloat162 h2;
                    h2.x = __float2bfloat16(c0);
                    h2.y = __float2bfloat16(c1);
                    *(__nv_bfloat162*)((__nv_bfloat16*)Cout + (size_t)gm * ldc + gn) = h2;
                } else if (EPI == EPI_ATT) {
                    float c0 = v0 * (1.f / (float)SEQ) + g_f[gm - gn + (SEQ - 1)];
                    float c1 = v1 * (1.f / (float)SEQ) + g_f[gm - gn - 1 + (SEQ - 1)];
                    c0 = fmaxf(c0, 0.f);
                    c1 = fmaxf(c1, 0.f);
                    __nv_bfloat16* cp = (__nv_bfloat16*)Cout + (long long)z * strideC;
                    __nv_bfloat162 h2;
                    h2.x = __float2bfloat16(c0 * c0);
                    h2.y = __float2bfloat16(c1 * c1);
                    *(__nv_bfloat162*)(cp + (size_t)gm * ldc + gn) = h2;
                } else if (EPI == EPI_O) {
                    float u0 = __bfloat162float(g_uvb[(size_t)(z * SEQ + gm) * PROJ + gn]);
                    float u1 = __bfloat162float(g_uvb[(size_t)(z * SEQ + gm) * PROJ + gn + 1]);
                    __nv_bfloat16* cp = (__nv_bfloat16*)Cout + (long long)z * strideC;
                    __nv_bfloat162 h2;
                    h2.x = __float2bfloat16(v0 * u0);
                    h2.y = __float2bfloat16(v1 * u1);
                    *(__nv_bfloat162*)(cp + (size_t)gm * ldc + gn) = h2;
                } else {
                    float c0 = v0 + bias[gn] + resid[(size_t)gm * DIM + gn];
                    float c1 = v1 + bias[gn + 1] + resid[(size_t)gm * DIM + gn + 1];
                    *(float2*)((float*)Cout + (size_t)gm * ldc + gn) = make_float2(c0, c1);
                }
            }
        }
    }
}

// -------------------- launch --------------------
extern "C" void kernel_launch(void* const* d_in, const int* in_sizes, int n_in,
                              void* d_out, int out_size) {
    const float* x          = (const float*)d_in[0];
    const float* W1         = (const float*)d_in[1];
    const float* b1         = (const float*)d_in[2];
    const float* W2         = (const float*)d_in[3];
    const float* b2         = (const float*)d_in[4];
    const float* rope_a     = (const float*)d_in[5];
    const float* rope_b     = (const float*)d_in[6];
    const float* gamma      = (const float*)d_in[7];
    const float* beta       = (const float*)d_in[8];
    const float* norm_scale = (const float*)d_in[9];
    float* out = (float*)d_out;

    void *p_xnb, *p_uvb, *p_w1t, *p_w2t, *p_qb, *p_kb, *p_attb, *p_vtb, *p_ob;
    cudaGetSymbolAddress(&p_xnb, g_xnb);
    cudaGetSymbolAddress(&p_uvb, g_uvb);
    cudaGetSymbolAddress(&p_w1t, g_w1t);
    cudaGetSymbolAddress(&p_w2t, g_w2t);
    cudaGetSymbolAddress(&p_qb, g_qb);
    cudaGetSymbolAddress(&p_kb, g_kb);
    cudaGetSymbolAddress(&p_attb, g_attb);
    cudaGetSymbolAddress(&p_vtb, g_vtb);
    cudaGetSymbolAddress(&p_ob, g_ob);

    constexpr int SMB = 1024 + STAGES * (BMT * 128 + 128 * 128);   // ~97KB
    cudaFuncSetAttribute(tc_gemm<EPI_G1>,  cudaFuncAttributeMaxDynamicSharedMemorySize, SMB);
    cudaFuncSetAttribute(tc_gemm<EPI_ATT>, cudaFuncAttributeMaxDynamicSharedMemorySize, SMB);
    cudaFuncSetAttribute(tc_gemm<EPI_O>,   cudaFuncAttributeMaxDynamicSharedMemorySize, SMB);
    cudaFuncSetAttribute(tc_gemm<EPI_OUT>, cudaFuncAttributeMaxDynamicSharedMemorySize, SMB);

    // launch 0
    rmsnorm_kernel<<<NROWS, 128>>>(x, norm_scale);
    // launch 1: toeplitz + W1^T + W2^T
    prep2_kernel<<<8 + (PROJ / 32) * (DIM / 32) + (DIM / 32) * (EXP / 32), 256>>>(
        W1, W2, rope_a, rope_b);
    // launch 2: uv = swish(xn @ W1 + b1)   M=16384 N=2176 K=512
    tc_gemm<EPI_G1><<<dim3(PROJ / 128, NROWS / BMT, 1), 256, SMB>>>(
        (const __nv_bfloat16*)p_xnb, DIM, 0,
        (const __nv_bfloat16*)p_w1t, DIM, 0,
        p_uvb, PROJ, 0, DIM / BKT, b1, nullptr);
    // launch 3: qkgen + vtrans
    qkv_kernel<<<(NROWS * SH) / 256 + (SEQ / 32) * (EXP / 32) * BATCH, 256>>>(gamma, beta);
    // launch 4: att = relu(q@k^T/SEQ + f)^2   per batch M=N=2048 K=128
    tc_gemm<EPI_ATT><<<dim3(SEQ / 128, SEQ / BMT, BATCH), 256, SMB>>>(
        (const __nv_bfloat16*)p_qb, SH, (long long)SEQ * SH,
        (const __nv_bfloat16*)p_kb, SH, (long long)SEQ * SH,
        p_attb, SEQ, (long long)SEQ * SEQ, SH / BKT, nullptr, nullptr);
    // launch 5 (profiled): o = u * (att @ v)  per batch M=2048 N=1024 K=2048
    tc_gemm<EPI_O><<<dim3(EXP / 128, SEQ / BMT, BATCH), 256, SMB>>>(
        (const __nv_bfloat16*)p_attb, SEQ, (long long)SEQ * SEQ,
        (const __nv_bfloat16*)p_vtb, SEQ, (long long)EXP * SEQ,
        p_ob, EXP, (long long)SEQ * EXP, SEQ / BKT, nullptr, nullptr);
    // launch 6: out = o @ W2 + b2 + x      M=16384 N=512 K=1024
    tc_gemm<EPI_OUT><<<dim3(DIM / 128, NROWS / BMT, 1), 256, SMB>>>(
        (const __nv_bfloat16*)p_ob, EXP, 0,
        (const __nv_bfloat16*)p_w2t, EXP, 0,
        out, DIM, 0, EXP / BKT, b2, x);
}

// round 8
// speedup vs baseline: 1.3727x; 1.0316x over previous
#include <cuda_runtime.h>
#include <cuda_bf16.h>
#include <math.h>
#include <stdint.h>

#define BATCH 8
#define SEQ   2048
#define DIM   512
#define SH    128
#define EXP   1024
#define PROJ  2176
#define NROWS (BATCH * SEQ)

#define BMT 128
#define BKT 64
#define STAGES 3

// -------------------- scratch --------------------
__device__ alignas(16) __nv_bfloat16 g_xnb[NROWS * DIM];
__device__ alignas(16) __nv_bfloat16 g_uvb[(size_t)NROWS * PROJ];
__device__ alignas(16) __nv_bfloat16 g_w1t[(size_t)PROJ * DIM];
__device__ alignas(16) __nv_bfloat16 g_w2t[(size_t)DIM * EXP];
__device__ alignas(16) __nv_bfloat16 g_qb [NROWS * SH];
__device__ alignas(16) __nv_bfloat16 g_kb [NROWS * SH];
__device__ alignas(16) __nv_bfloat16 g_attb[(size_t)BATCH * SEQ * SEQ];
__device__ alignas(16) __nv_bfloat16 g_ob  [(size_t)NROWS * EXP];
__device__ float g_f[2 * SEQ - 1];

// -------------------- helpers --------------------
__device__ __forceinline__ uint32_t smem_u32(const void* p) {
    uint32_t a;
    asm("{ .reg .u64 t; cvta.to.shared.u64 t, %1; cvt.u32.u64 %0, t; }" : "=r"(a) : "l"(p));
    return a;
}
__device__ __forceinline__ void cp16s(uint32_t saddr, const void* g) {
    asm volatile("cp.async.cg.shared.global [%0], [%1], 16;\n" :: "r"(saddr), "l"(g));
}
#define CP_COMMIT() asm volatile("cp.async.commit_group;\n" ::: "memory")
#define SWZ(o) ((o) ^ (((o) >> 3) & 0x70))
// swizzle for 256-byte rows: xor 16B-unit index with row%8
__device__ __forceinline__ uint32_t swz256(uint32_t o) {
    return o ^ (((o >> 8) & 7) << 4);
}

__device__ __forceinline__ void mma16816(float* c, const uint32_t* a, const uint32_t* b) {
    asm volatile(
        "mma.sync.aligned.m16n8k16.row.col.f32.bf16.bf16.f32 "
        "{%0,%1,%2,%3},{%4,%5,%6,%7},{%8,%9},{%0,%1,%2,%3};\n"
        : "+f"(c[0]), "+f"(c[1]), "+f"(c[2]), "+f"(c[3])
        : "r"(a[0]), "r"(a[1]), "r"(a[2]), "r"(a[3]), "r"(b[0]), "r"(b[1]));
}
__device__ __forceinline__ void ldsm4(uint32_t* r, uint32_t addr) {
    asm volatile("ldmatrix.sync.aligned.m8n8.x4.shared.b16 {%0,%1,%2,%3}, [%4];"
        : "=r"(r[0]), "=r"(r[1]), "=r"(r[2]), "=r"(r[3]) : "r"(addr));
}
__device__ __forceinline__ void ldsm4t(uint32_t* r, uint32_t addr) {
    asm volatile("ldmatrix.sync.aligned.m8n8.x4.trans.shared.b16 {%0,%1,%2,%3}, [%4];"
        : "=r"(r[0]), "=r"(r[1]), "=r"(r[2]), "=r"(r[3]) : "r"(addr));
}

// -------------------- kernel 0: rmsnorm -> bf16 --------------------
__global__ void rmsnorm_kernel(const float* __restrict__ x,
                               const float* __restrict__ ns_p) {
    int row = blockIdx.x;
    const float4* xr = (const float4*)(x + (size_t)row * DIM);
    __nv_bfloat162* outr = (__nv_bfloat162*)(g_xnb + (size_t)row * DIM);
    float4 v = xr[threadIdx.x];
    float s = v.x * v.x + v.y * v.y + v.z * v.z + v.w * v.w;
    __shared__ float warp_s[4];
    #pragma unroll
    for (int off = 16; off > 0; off >>= 1) s += __shfl_down_sync(0xffffffffu, s, off);
    int lane = threadIdx.x & 31, wid = threadIdx.x >> 5;
    if (lane == 0) warp_s[wid] = s;
    __syncthreads();
    if (wid == 0) {
        float t = (lane < 4) ? warp_s[lane] : 0.f;
        #pragma unroll
        for (int off = 2; off > 0; off >>= 1) t += __shfl_down_sync(0xffffffffu, t, off);
        if (lane == 0) warp_s[0] = t;
    }
    __syncthreads();
    float scale = rsqrtf(warp_s[0] * (1.f / (float)DIM) + 1e-6f) * ns_p[0];
    __nv_bfloat162 h0, h1;
    h0.x = __float2bfloat16(v.x * scale);
    h0.y = __float2bfloat16(v.y * scale);
    h1.x = __float2bfloat16(v.z * scale);
    h1.y = __float2bfloat16(v.w * scale);
    outr[threadIdx.x * 2] = h0;
    outr[threadIdx.x * 2 + 1] = h1;
}

// -------------------- kernel 1: toeplitz + W1^T + W2^T (fused) ------------
__global__ void prep2_kernel(const float* __restrict__ W1, const float* __restrict__ W2,
                             const float* __restrict__ ra, const float* __restrict__ rb) {
    __shared__ float sp[SEQ / 2];
    __shared__ float sr[SEQ / 2];
    __shared__ float tt[32][33];
    int bx = blockIdx.x;
    if (bx < 8) {
        for (int i = threadIdx.x; i < SEQ / 2; i += blockDim.x) {
            float a1 = ra[i], a2 = ra[i + SEQ / 2];
            float b1v = rb[i], b2v = rb[i + SEQ / 2];
            sp[i] = a1 * b1v + a2 * b2v;
            sr[i] = a2 * b1v - a1 * b2v;
        }
        __syncthreads();
        int d = bx * 256 + threadIdx.x;
        float sumc = 0.f, sums = 0.f;
        const float log1e4 = 9.210340371976184f;
        for (int i = 0; i < SEQ / 2; i++) {
            float theta = expf(-((float)i * (1.f / (SEQ / 2))) * log1e4);
            float s, c;
            sincosf((float)d * theta, &s, &c);
            sumc += sp[i] * c;
            sums += sr[i] * s;
        }
        g_f[(SEQ - 1) + d] = sumc - sums;
        g_f[(SEQ - 1) - d] = sumc + sums;
        return;
    }
    const float* in;
    __nv_bfloat16* out;
    int rows, cols, bxx, byy;
    if (bx < 8 + (PROJ / 32) * (DIM / 32)) {
        int b = bx - 8;
        in = W1; out = g_w1t; rows = DIM; cols = PROJ;
        bxx = b % (PROJ / 32); byy = b / (PROJ / 32);
    } else {
        int b = bx - 8 - (PROJ / 32) * (DIM / 32);
        in = W2; out = g_w2t; rows = EXP; cols = DIM;
        bxx = b % (DIM / 32); byy = b / (DIM / 32);
    }
    int r0 = byy * 32, c0 = bxx * 32;
    int tx = threadIdx.x & 31, ty = threadIdx.x >> 5;
    #pragma unroll
    for (int i = ty; i < 32; i += 8)
        tt[i][tx] = in[(size_t)(r0 + i) * cols + c0 + tx];
    __syncthreads();
    #pragma unroll
    for (int i = ty; i < 32; i += 8)
        out[(size_t)(c0 + i) * rows + r0 + tx] = __float2bfloat16(tt[tx][i]);
}

// -------------------- kernel 3: qkgen --------------------
__global__ void qkgen_kernel(const float* __restrict__ gamma,
                             const float* __restrict__ beta) {
    int idx = blockIdx.x * blockDim.x + threadIdx.x;
    int j = idx & (SH - 1);
    int row = idx >> 7;
    float base = __bfloat162float(g_uvb[(size_t)row * PROJ + 2 * EXP + j]);
    g_qb[idx] = __float2bfloat16(base * gamma[j] + beta[j]);
    g_kb[idx] = __float2bfloat16(base * gamma[SH + j] + beta[SH + j]);
}

// -------------------- HMMA GEMM, BN=128, 3 stages, 2 CTA/SM ------------
// NT (BNN=0): C[m][n] = sum_k A[m][k]*B[n][k]
// NN (BNN=1): C[m][n] = sum_k A[m][k]*B[k][n]   (B loaded via ldmatrix.trans)
enum { EPI_G1 = 0, EPI_ATT = 1, EPI_O = 2, EPI_OUT = 3 };

template <int EPI, int BNN>
__global__ void __launch_bounds__(256, 2) tc_gemm(
    const __nv_bfloat16* __restrict__ A, int lda, long long strideA,
    const __nv_bfloat16* __restrict__ Bm, int ldb, long long strideB,
    void* __restrict__ Cout, int ldc, long long strideC,
    int KT,
    const float* __restrict__ bias,
    const float* __restrict__ resid) {
    constexpr int BN = 128;
    constexpr int MT = 2;
    constexpr int A_BYTES = BMT * 128;
    constexpr int B_BYTES = BN * 128;
    constexpr int STAGE_BYTES = A_BYTES + B_BYTES;

    extern __shared__ char smem[];
    uint32_t sb = (smem_u32(smem) + 1023) & ~1023u;
    int t = threadIdx.x;
    int warp = t >> 5, lane = t & 31;
    int wn = warp & 1, wm = warp >> 1;
    int z = blockIdx.z;

    const __nv_bfloat16* Ag = A + (long long)z * strideA + (long long)(blockIdx.y * BMT) * lda;
    const __nv_bfloat16* Bg;
    if (BNN) Bg = Bm + (long long)z * strideB + blockIdx.x * BN;             // column offset
    else     Bg = Bm + (long long)z * strideB + (long long)(blockIdx.x * BN) * ldb;

    uint32_t a_off = (uint32_t)((wm * MT * 16 + (lane & 15)) * 128 + (lane & 16));
    uint32_t b_off = (uint32_t)((wn * 64 + (lane & 7) + ((lane >> 1) & 8)) * 128 + (lane & 8) * 2);
    // NN trans-load lane mapping
    int tsel = lane >> 3, rloc = lane & 7;
    int k_in = (tsel & 1) * 8 + rloc;       // 0..15
    int n_in = (tsel >> 1) * 8;             // 0 or 8

    // f staging for EPI_ATT
    uint32_t fs_base = sb + STAGES * STAGE_BYTES;
    if (EPI == EPI_ATT) {
        if (t < 255) {
            int d0 = blockIdx.y * BMT - blockIdx.x * BN - 127 + (SEQ - 1);
            float v = g_f[d0 + t];
            asm volatile("st.shared.f32 [%0], %1;" :: "r"(fs_base + t * 4), "f"(v));
        }
    }

    auto load_tile = [&](int j) {
        int s = j % STAGES;
        uint32_t sA = sb + s * STAGE_BYTES;
        uint32_t sB = sA + A_BYTES;
        const __nv_bfloat16* Asrc = Ag + j * BKT;
        #pragma unroll
        for (int i = 0; i < 4; i++) {
            int c = t + i * 256;
            int row = c >> 3, kc = c & 7;
            cp16s(sA + SWZ(row * 128 + kc * 16), Asrc + (long long)row * lda + kc * 8);
        }
        if (BNN) {
            const __nv_bfloat16* Bsrc = Bg + (long long)(j * BKT) * ldb;
            #pragma unroll
            for (int i = 0; i < 4; i++) {
                int c = t + i * 256;
                int row = c >> 4, kc = c & 15;
                cp16s(sB + swz256(row * 256 + kc * 16), Bsrc + (long long)row * ldb + kc * 8);
            }
        } else {
            const __nv_bfloat16* Bsrc = Bg + j * BKT;
            #pragma unroll
            for (int i = 0; i < 4; i++) {
                int c = t + i * 256;
                int row = c >> 3, kc = c & 7;
                cp16s(sB + SWZ(row * 128 + kc * 16), Bsrc + (long long)row * ldb + kc * 8);
            }
        }
        CP_COMMIT();
    };

    float acc[MT][8][4];
    #pragma unroll
    for (int i = 0; i < MT; i++)
        #pragma unroll
        for (int j = 0; j < 8; j++)
            #pragma unroll
            for (int l = 0; l < 4; l++) acc[i][j][l] = 0.f;

    load_tile(0);
    if (KT > 1) load_tile(1);

    for (int kt = 0; kt < KT; kt++) {
        if (kt + 1 < KT) asm volatile("cp.async.wait_group 1;\n" ::: "memory");
        else             asm volatile("cp.async.wait_group 0;\n" ::: "memory");
        __syncthreads();

        if (kt + 2 < KT) load_tile(kt + 2);

        int s = kt % STAGES;
        uint32_t sA = sb + s * STAGE_BYTES;
        uint32_t sB = sA + A_BYTES;
        #pragma unroll
        for (int ks = 0; ks < 4; ks++) {
            uint32_t a[MT][4], b[8][2];
            #pragma unroll
            for (int mt = 0; mt < MT; mt++)
                ldsm4(a[mt], sA + SWZ(a_off + mt * 2048 + ks * 32));
            #pragma unroll
            for (int i = 0; i < 4; i++) {
                uint32_t r[4];
                if (BNN) {
                    uint32_t byte = (uint32_t)((ks * 16 + k_in) * 256 +
                                               (wn * 64 + i * 16 + n_in) * 2);
                    ldsm4t(r, sB + swz256(byte));
                } else {
                    ldsm4(r, sB + SWZ(b_off + i * 2048 + ks * 32));
                }
                b[2 * i][0] = r[0]; b[2 * i][1] = r[1];
                b[2 * i + 1][0] = r[2]; b[2 * i + 1][1] = r[3];
            }
            #pragma unroll
            for (int mt = 0; mt < MT; mt++)
                #pragma unroll
                for (int nt = 0; nt < 8; nt++) mma16816(acc[mt][nt], a[mt], b[nt]);
        }
    }

    // -------- epilogue --------
    int fr = lane >> 2, fc = (lane & 3) * 2;
    int bm0 = blockIdx.y * BMT + wm * MT * 16;
    int bn0 = blockIdx.x * BN + wn * 64;
    #pragma unroll
    for (int mt = 0; mt < MT; mt++) {
        #pragma unroll
        for (int nt = 0; nt < 8; nt++) {
            #pragma unroll
            for (int half = 0; half < 2; half++) {
                int gm = bm0 + mt * 16 + fr + half * 8;
                int gn = bn0 + nt * 8 + fc;
                float v0 = acc[mt][nt][half * 2 + 0];
                float v1 = acc[mt][nt][half * 2 + 1];
                if (EPI == EPI_G1) {
                    float c0 = v0 + bias[gn], c1 = v1 + bias[gn + 1];
                    c0 = c0 / (1.f + expf(-c0));
                    c1 = c1 / (1.f + expf(-c1));
                    __nv_bfloat162 h2;
                    h2.x = __float2bfloat16(c0);
                    h2.y = __float2bfloat16(c1);
                    *(__nv_bfloat162*)((__nv_bfloat16*)Cout + (size_t)gm * ldc + gn) = h2;
                } else if (EPI == EPI_ATT) {
                    int lm = gm - blockIdx.y * BMT, ln = gn - blockIdx.x * BN;
                    float f0, f1;
                    asm volatile("ld.shared.f32 %0, [%1];" : "=f"(f0)
                                 : "r"(fs_base + (lm - ln + 127) * 4));
                    asm volatile("ld.shared.f32 %0, [%1];" : "=f"(f1)
                                 : "r"(fs_base + (lm - ln + 126) * 4));
                    float c0 = v0 * (1.f / (float)SEQ) + f0;
                    float c1 = v1 * (1.f / (float)SEQ) + f1;
                    c0 = fmaxf(c0, 0.f);
                    c1 = fmaxf(c1, 0.f);
                    __nv_bfloat16* cp = (__nv_bfloat16*)Cout + (long long)z * strideC;
                    __nv_bfloat162 h2;
                    h2.x = __float2bfloat16(c0 * c0);
                    h2.y = __float2bfloat16(c1 * c1);
                    *(__nv_bfloat162*)(cp + (size_t)gm * ldc + gn) = h2;
                } else if (EPI == EPI_O) {
                    float u0 = __bfloat162float(g_uvb[(size_t)(z * SEQ + gm) * PROJ + gn]);
                    float u1 = __bfloat162float(g_uvb[(size_t)(z * SEQ + gm) * PROJ + gn + 1]);
                    __nv_bfloat16* cp = (__nv_bfloat16*)Cout + (long long)z * strideC;
                    __nv_bfloat162 h2;
                    h2.x = __float2bfloat16(v0 * u0);
                    h2.y = __float2bfloat16(v1 * u1);
                    *(__nv_bfloat162*)(cp + (size_t)gm * ldc + gn) = h2;
                } else {
                    float c0 = v0 + bias[gn] + resid[(size_t)gm * DIM + gn];
                    float c1 = v1 + bias[gn + 1] + resid[(size_t)gm * DIM + gn + 1];
                    *(float2*)((float*)Cout + (size_t)gm * ldc + gn) = make_float2(c0, c1);
                }
            }
        }
    }
}

// -------------------- launch --------------------
extern "C" void kernel_launch(void* const* d_in, const int* in_sizes, int n_in,
                              void* d_out, int out_size) {
    const float* x          = (const float*)d_in[0];
    const float* W1         = (const float*)d_in[1];
    const float* b1         = (const float*)d_in[2];
    const float* W2         = (const float*)d_in[3];
    const float* b2         = (const float*)d_in[4];
    const float* rope_a     = (const float*)d_in[5];
    const float* rope_b     = (const float*)d_in[6];
    const float* gamma      = (const float*)d_in[7];
    const float* beta       = (const float*)d_in[8];
    const float* norm_scale = (const float*)d_in[9];
    float* out = (float*)d_out;

    void *p_xnb, *p_uvb, *p_w1t, *p_w2t, *p_qb, *p_kb, *p_attb, *p_ob;
    cudaGetSymbolAddress(&p_xnb, g_xnb);
    cudaGetSymbolAddress(&p_uvb, g_uvb);
    cudaGetSymbolAddress(&p_w1t, g_w1t);
    cudaGetSymbolAddress(&p_w2t, g_w2t);
    cudaGetSymbolAddress(&p_qb, g_qb);
    cudaGetSymbolAddress(&p_kb, g_kb);
    cudaGetSymbolAddress(&p_attb, g_attb);
    cudaGetSymbolAddress(&p_ob, g_ob);

    constexpr int SMB = 2048 + STAGES * (BMT * 128 + 128 * 128);   // ~98.3KB (incl f stage)
    cudaFuncSetAttribute((const void*)tc_gemm<EPI_G1, 0>,  cudaFuncAttributeMaxDynamicSharedMemorySize, SMB);
    cudaFuncSetAttribute((const void*)tc_gemm<EPI_ATT, 0>, cudaFuncAttributeMaxDynamicSharedMemorySize, SMB);
    cudaFuncSetAttribute((const void*)tc_gemm<EPI_O, 1>,   cudaFuncAttributeMaxDynamicSharedMemorySize, SMB);
    cudaFuncSetAttribute((const void*)tc_gemm<EPI_OUT, 0>, cudaFuncAttributeMaxDynamicSharedMemorySize, SMB);

    // launch 0
    rmsnorm_kernel<<<NROWS, 128>>>(x, norm_scale);
    // launch 1: toeplitz + W1^T + W2^T
    prep2_kernel<<<8 + (PROJ / 32) * (DIM / 32) + (DIM / 32) * (EXP / 32), 256>>>(
        W1, W2, rope_a, rope_b);
    // launch 2: uv = swish(xn @ W1 + b1)   M=16384 N=2176 K=512
    tc_gemm<EPI_G1, 0><<<dim3(PROJ / 128, NROWS / BMT, 1), 256, SMB>>>(
        (const __nv_bfloat16*)p_xnb, DIM, 0,
        (const __nv_bfloat16*)p_w1t, DIM, 0,
        p_uvb, PROJ, 0, DIM / BKT, b1, nullptr);
    // launch 3: qkgen
    qkgen_kernel<<<(NROWS * SH) / 256, 256>>>(gamma, beta);
    // launch 4: att = relu(q@k^T/SEQ + f)^2   per batch M=N=2048 K=128
    tc_gemm<EPI_ATT, 0><<<dim3(SEQ / 128, SEQ / BMT, BATCH), 256, SMB>>>(
        (const __nv_bfloat16*)p_qb, SH, (long long)SEQ * SH,
        (const __nv_bfloat16*)p_kb, SH, (long long)SEQ * SH,
        p_attb, SEQ, (long long)SEQ * SEQ, SH / BKT, nullptr, nullptr);
    // launch 5 (profiled): o = u * (att @ v)  per batch M=2048 N=1024 K=2048 (v read NN)
    tc_gemm<EPI_O, 1><<<dim3(EXP / 128, SEQ / BMT, BATCH), 256, SMB>>>(
        (const __nv_bfloat16*)p_attb, SEQ, (long long)SEQ * SEQ,
        (const __nv_bfloat16*)p_uvb + EXP, PROJ, (long long)SEQ * PROJ,
        p_ob, EXP, (long long)SEQ * EXP, SEQ / BKT, nullptr, nullptr);
    // launch 6: out = o @ W2 + b2 + x      M=16384 N=512 K=1024
    tc_gemm<EPI_OUT, 0><<<dim3(DIM / 128, NROWS / BMT, 1), 256, SMB>>>(
        (const __nv_bfloat16*)p_ob, EXP, 0,
        (const __nv_bfloat16*)p_w2t, EXP, 0,
        out, DIM, 0, EXP / BKT, b2, x);
}